// round 5
// baseline (speedup 1.0000x reference)
#include <cuda_runtime.h>

#define B_  256
#define T_  2048
#define H_  64
#define O_  2
#define NROWS (B_ * T_)
#define PF  4   // fused-scan xin prefetch depth (T_ % PF == 0)

// Scratch (device globals — no allocation allowed in kernel_launch)
__device__ float g_bufA[NROWS * H_];
__device__ float g_bufB[NROWS * H_];

// ---------- packed f32x2 helpers (sm_103a FFMA2 path) ----------
static __device__ __forceinline__ unsigned long long pack2(float lo, float hi) {
    unsigned long long r;
    asm("mov.b64 %0, {%1, %2};" : "=l"(r) : "f"(lo), "f"(hi));
    return r;
}
static __device__ __forceinline__ void unpack2(unsigned long long v, float& a, float& b) {
    asm("mov.b64 {%0, %1}, %2;" : "=f"(a), "=f"(b) : "l"(v));
}
static __device__ __forceinline__ unsigned long long fma2(unsigned long long a,
                                                          unsigned long long b,
                                                          unsigned long long c) {
    unsigned long long d;
    asm("fma.rn.f32x2 %0, %1, %2, %3;" : "=l"(d) : "l"(a), "l"(b), "l"(c));
    return d;
}
static __device__ __forceinline__ unsigned long long add2(unsigned long long a,
                                                          unsigned long long b) {
    unsigned long long d;
    asm("add.rn.f32x2 %0, %1, %2;" : "=l"(d) : "l"(a), "l"(b));
    return d;
}

// Fast tanh, rel err ~1e-7, saturates correctly.
static __device__ __forceinline__ float fast_tanh(float x) {
    float e = __expf(2.0f * x);
    return 1.0f - __fdividef(2.0f, e + 1.0f);
}

#define NAMED_BAR(id, cnt) asm volatile("bar.sync %0, %1;" :: "r"(id), "r"(cnt) : "memory")

// ============================================================================
// gemm64: out[r][j] = sum_k in[r][k] * W[j][k] + ba[j] + bb[j]
// Warp handles 2 rows/iter, K-paired f32x2, broadcast LDS.128 staging.
// ============================================================================
__global__ void __launch_bounds__(128) gemm64_kernel(
    const float* __restrict__ in, const float* __restrict__ W,
    const float* __restrict__ ba, const float* __restrict__ bb,
    float* __restrict__ out, int nrows)
{
    __shared__ __align__(16) unsigned long long xsm[4][2][2][32];
    const int l   = threadIdx.x & 31;
    const int wrp = threadIdx.x >> 5;
    const unsigned long long* Wu = (const unsigned long long*)W;
    const unsigned long long* Iu = (const unsigned long long*)in;

    unsigned long long wl[32], wh[32];
#pragma unroll
    for (int k = 0; k < 32; k++) {
        wl[k] = Wu[l * 32 + k];
        wh[k] = Wu[(l + 32) * 32 + k];
    }
    const float biasl = ba[l] + bb[l];
    const float biash = ba[l + 32] + bb[l + 32];

    const int warpId = blockIdx.x * 4 + wrp;
    const int nw     = gridDim.x * 4;
    const long stride = 2L * nw;

    long r = 2L * warpId;
    if (r >= nrows) return;
    unsigned long long xv0 = Iu[r * 32 + l];
    unsigned long long xv1 = (r + 1 < nrows) ? Iu[(r + 1) * 32 + l] : 0ull;
    int buf = 0;

    while (r < nrows) {
        xsm[wrp][buf][0][l] = xv0;
        xsm[wrp][buf][1][l] = xv1;
        __syncwarp();

        long rn = r + stride;
        if (rn < nrows) {
            xv0 = Iu[rn * 32 + l];
            xv1 = (rn + 1 < nrows) ? Iu[(rn + 1) * 32 + l] : 0ull;
        }

        unsigned long long a0 = pack2(biasl, 0.f), a1 = 0ull;
        unsigned long long c0 = pack2(biash, 0.f), c1 = 0ull;
        unsigned long long d0 = pack2(biasl, 0.f), d1 = 0ull;
        unsigned long long e0 = pack2(biash, 0.f), e1 = 0ull;
        const ulonglong2* xp0 = (const ulonglong2*)&xsm[wrp][buf][0][0];
        const ulonglong2* xp1 = (const ulonglong2*)&xsm[wrp][buf][1][0];
#pragma unroll
        for (int k = 0; k < 32; k += 2) {
            ulonglong2 v0 = xp0[k >> 1];
            ulonglong2 v1 = xp1[k >> 1];
            a0 = fma2(wl[k],     v0.x, a0);
            a1 = fma2(wl[k + 1], v0.y, a1);
            c0 = fma2(wh[k],     v0.x, c0);
            c1 = fma2(wh[k + 1], v0.y, c1);
            d0 = fma2(wl[k],     v1.x, d0);
            d1 = fma2(wl[k + 1], v1.y, d1);
            e0 = fma2(wh[k],     v1.x, e0);
            e1 = fma2(wh[k + 1], v1.y, e1);
        }
        float s0, s1, t0, t1, u0, u1, q0, q1;
        unpack2(add2(a0, a1), s0, s1);
        unpack2(add2(c0, c1), t0, t1);
        unpack2(add2(d0, d1), u0, u1);
        unpack2(add2(e0, e1), q0, q1);
        out[r * 64 + l]      = s0 + s1;
        out[r * 64 + 32 + l] = t0 + t1;
        if (r + 1 < nrows) {
            out[(r + 1) * 64 + l]      = u0 + u1;
            out[(r + 1) * 64 + 32 + l] = q0 + q1;
        }

        buf ^= 1;
        r = rn;
    }
}

// ============================================================================
// fused_scan (software-pipelined): iteration i computes, CONCURRENTLY,
//   h0_i     = tanh(x_i + W_hh0 h0_{i-1})
//   h1_{i-1} = tanh(W_ih1 h0_{i-1} + b1 + W_hh1 h1_{i-2})
// Both read only published state -> all 3 matvecs interleave in one fma block
// (h0_{i-1} loaded ONCE feeds both W_hh0 and W_ih1), ONE barrier per step.
// Block = 128 threads = 2 batches x 2 warps; per-batch named barrier.
// Epilogue computes h1_{T-1}.
// ============================================================================
__global__ void __launch_bounds__(128) fused_scan_kernel(
    const float* __restrict__ xin0,
    const float* __restrict__ Whh0, const float* __restrict__ Wih1,
    const float* __restrict__ Whh1,
    const float* __restrict__ b_ih1, const float* __restrict__ b_hh1,
    float* __restrict__ h1out)
{
    __shared__ __align__(16) float h0sm[2][2][64];
    __shared__ __align__(16) float h1sm[2][2][64];
    const int l    = threadIdx.x & 31;
    const int wid  = threadIdx.x >> 5;
    const int bl   = wid >> 1;        // batch slot (0..1)
    const int half = wid & 1;
    const int j    = half * 32 + l;   // owned output
    const int b    = blockIdx.x * 2 + bl;
    const int barid = bl + 1;

    const unsigned long long* W0u = (const unsigned long long*)Whh0;
    const unsigned long long* Wxu = (const unsigned long long*)Wih1;
    const unsigned long long* W1u = (const unsigned long long*)Whh1;
    unsigned long long w0[32], wx[32], w1[32];
#pragma unroll
    for (int k = 0; k < 32; k++) {
        w0[k] = W0u[j * 32 + k];
        wx[k] = Wxu[j * 32 + k];
        w1[k] = W1u[j * 32 + k];
    }
    const float bias1 = b_ih1[j] + b_hh1[j];

    h0sm[bl][0][j] = 0.f;   // h0_{-1}
    h1sm[bl][0][j] = 0.f;   // h1_{-2} (placeholder)

    const float* xb = xin0  + (long)b * T_ * 64;
    float*       hb = h1out + (long)b * T_ * 64;

    float xs[PF];
#pragma unroll
    for (int s = 0; s < PF; s++) xs[s] = xb[s * 64 + j];

    NAMED_BAR(barid, 64);

    int p = 0;
    for (int tb = 0; tb < T_; tb += PF) {
#pragma unroll
        for (int u = 0; u < PF; u++) {
            const int i = tb + u;
            const float xv = xs[u];
            if (i + PF < T_) xs[u] = xb[(i + PF) * 64 + j];

            // h0sm[bl][p] = h0_{i-1}, h1sm[bl][p] = h1_{i-2}
            unsigned long long a0 = pack2(xv, 0.f), a1 = 0ull;     // h0_i
            unsigned long long c0 = pack2(bias1, 0.f), c1 = 0ull;  // Wih1.h0_{i-1}
            unsigned long long d0 = 0ull, d1 = 0ull;               // Whh1.h1_{i-2}
            const ulonglong2* hp0 = (const ulonglong2*)&h0sm[bl][p][0];
            const ulonglong2* hp1 = (const ulonglong2*)&h1sm[bl][p][0];
#pragma unroll
            for (int k = 0; k < 32; k += 2) {
                ulonglong2 v = hp0[k >> 1];   // h0_{i-1}: ONE load, two uses
                ulonglong2 g = hp1[k >> 1];   // h1_{i-2}
                a0 = fma2(w0[k],     v.x, a0);
                a1 = fma2(w0[k + 1], v.y, a1);
                c0 = fma2(wx[k],     v.x, c0);
                c1 = fma2(wx[k + 1], v.y, c1);
                d0 = fma2(w1[k],     g.x, d0);
                d1 = fma2(w1[k + 1], g.y, d1);
            }
            float s0, s1, e0, e1;
            unpack2(add2(a0, a1), s0, s1);
            unpack2(add2(add2(c0, c1), add2(d0, d1)), e0, e1);
            const float h0v = fast_tanh(s0 + s1);
            float h1v = fast_tanh(e0 + e1);     // = h1_{i-1}

            if (i) hb[(i - 1) * 64 + j] = h1v;  // t = i-1
            else   h1v = 0.f;                   // h1_{-1} := 0

            h0sm[bl][p ^ 1][j] = h0v;
            h1sm[bl][p ^ 1][j] = h1v;
            NAMED_BAR(barid, 64);
            p ^= 1;
        }
    }

    // Epilogue: h1_{T-1} = tanh(Wih1 h0_{T-1} + b1 + Whh1 h1_{T-2})
    {
        unsigned long long c0 = pack2(bias1, 0.f), c1 = 0ull;
        unsigned long long d0 = 0ull, d1 = 0ull;
        const ulonglong2* hp0 = (const ulonglong2*)&h0sm[bl][p][0];
        const ulonglong2* hp1 = (const ulonglong2*)&h1sm[bl][p][0];
#pragma unroll
        for (int k = 0; k < 32; k += 2) {
            ulonglong2 v = hp0[k >> 1];
            ulonglong2 g = hp1[k >> 1];
            c0 = fma2(wx[k],     v.x, c0);
            c1 = fma2(wx[k + 1], v.y, c1);
            d0 = fma2(w1[k],     g.x, d0);
            d1 = fma2(w1[k + 1], g.y, d1);
        }
        float e0, e1;
        unpack2(add2(add2(c0, c1), add2(d0, d1)), e0, e1);
        hb[(T_ - 1) * 64 + j] = fast_tanh(e0 + e1);
    }
}

// ============================================================================
// head: z = relu(h W1^T + b1); out = z W2^T + b2  (O=2). 2 rows/iter.
// ============================================================================
__global__ void __launch_bounds__(128) head_kernel(
    const float* __restrict__ hin, const float* __restrict__ W1,
    const float* __restrict__ b1, const float* __restrict__ W2,
    const float* __restrict__ b2, float* __restrict__ out, int nrows)
{
    __shared__ __align__(16) unsigned long long xsm[4][2][2][32];
    const int l   = threadIdx.x & 31;
    const int wrp = threadIdx.x >> 5;
    const unsigned long long* Wu = (const unsigned long long*)W1;
    const unsigned long long* Iu = (const unsigned long long*)hin;

    unsigned long long wl[32], wh[32];
#pragma unroll
    for (int k = 0; k < 32; k++) {
        wl[k] = Wu[l * 32 + k];
        wh[k] = Wu[(l + 32) * 32 + k];
    }
    const float biasl = b1[l], biash = b1[l + 32];
    const float w20l = W2[l],      w20h = W2[32 + l];
    const float w21l = W2[64 + l], w21h = W2[96 + l];
    const float b20 = b2[0], b21 = b2[1];

    const int warpId = blockIdx.x * 4 + wrp;
    const int nw     = gridDim.x * 4;
    const long stride = 2L * nw;

    long r = 2L * warpId;
    if (r >= nrows) return;
    unsigned long long xv0 = Iu[r * 32 + l];
    unsigned long long xv1 = (r + 1 < nrows) ? Iu[(r + 1) * 32 + l] : 0ull;
    int buf = 0;

    while (r < nrows) {
        xsm[wrp][buf][0][l] = xv0;
        xsm[wrp][buf][1][l] = xv1;
        __syncwarp();

        long rn = r + stride;
        if (rn < nrows) {
            xv0 = Iu[rn * 32 + l];
            xv1 = (rn + 1 < nrows) ? Iu[(rn + 1) * 32 + l] : 0ull;
        }

        unsigned long long a0 = pack2(biasl, 0.f), a1 = 0ull;
        unsigned long long c0 = pack2(biash, 0.f), c1 = 0ull;
        unsigned long long d0 = pack2(biasl, 0.f), d1 = 0ull;
        unsigned long long e0 = pack2(biash, 0.f), e1 = 0ull;
        const ulonglong2* xp0 = (const ulonglong2*)&xsm[wrp][buf][0][0];
        const ulonglong2* xp1 = (const ulonglong2*)&xsm[wrp][buf][1][0];
#pragma unroll
        for (int k = 0; k < 32; k += 2) {
            ulonglong2 v0 = xp0[k >> 1];
            ulonglong2 v1 = xp1[k >> 1];
            a0 = fma2(wl[k],     v0.x, a0);
            a1 = fma2(wl[k + 1], v0.y, a1);
            c0 = fma2(wh[k],     v0.x, c0);
            c1 = fma2(wh[k + 1], v0.y, c1);
            d0 = fma2(wl[k],     v1.x, d0);
            d1 = fma2(wl[k + 1], v1.y, d1);
            e0 = fma2(wh[k],     v1.x, e0);
            e1 = fma2(wh[k + 1], v1.y, e1);
        }
        float s0, s1, t0, t1, u0, u1, q0, q1;
        unpack2(add2(a0, a1), s0, s1);
        unpack2(add2(c0, c1), t0, t1);
        unpack2(add2(d0, d1), u0, u1);
        unpack2(add2(e0, e1), q0, q1);

        float z0 = fmaxf(s0 + s1, 0.f);
        float z1 = fmaxf(t0 + t1, 0.f);
        float y0 = fmaxf(u0 + u1, 0.f);
        float y1 = fmaxf(q0 + q1, 0.f);

        float p0 = z0 * w20l + z1 * w20h;
        float p1 = z0 * w21l + z1 * w21h;
        float p2 = y0 * w20l + y1 * w20h;
        float p3 = y0 * w21l + y1 * w21h;
#pragma unroll
        for (int off = 16; off; off >>= 1) {
            p0 += __shfl_xor_sync(0xffffffffu, p0, off);
            p1 += __shfl_xor_sync(0xffffffffu, p1, off);
            p2 += __shfl_xor_sync(0xffffffffu, p2, off);
            p3 += __shfl_xor_sync(0xffffffffu, p3, off);
        }
        if (l == 0) {
            *reinterpret_cast<float2*>(&out[r * 2]) = make_float2(p0 + b20, p1 + b21);
            if (r + 1 < nrows)
                *reinterpret_cast<float2*>(&out[(r + 1) * 2]) = make_float2(p2 + b20, p3 + b21);
        }

        buf ^= 1;
        r = rn;
    }
}

// ============================================================================
extern "C" void kernel_launch(void* const* d_in, const int* in_sizes, int n_in,
                              void* d_out, int out_size)
{
    const float* x     = (const float*)d_in[0];
    const float* W_ih0 = (const float*)d_in[1];
    const float* W_hh0 = (const float*)d_in[2];
    const float* b_ih0 = (const float*)d_in[3];
    const float* b_hh0 = (const float*)d_in[4];
    const float* W_ih1 = (const float*)d_in[5];
    const float* W_hh1 = (const float*)d_in[6];
    const float* b_ih1 = (const float*)d_in[7];
    const float* b_hh1 = (const float*)d_in[8];
    const float* W1    = (const float*)d_in[9];
    const float* b1    = (const float*)d_in[10];
    const float* W2    = (const float*)d_in[11];
    const float* b2    = (const float*)d_in[12];
    float* out = (float*)d_out;

    static float* bufA = nullptr;
    static float* bufB = nullptr;
    if (!bufA) {
        cudaGetSymbolAddress((void**)&bufA, g_bufA);
        cudaGetSymbolAddress((void**)&bufB, g_bufB);
    }

    const int GRID = 1184;

    // xin0 = x W_ih0^T + b_ih0 + b_hh0
    gemm64_kernel<<<GRID, 128>>>(x, W_ih0, b_ih0, b_hh0, bufA, NROWS);
    // both RNN layers, software-pipelined -> h1
    fused_scan_kernel<<<B_ / 2, 128>>>(bufA, W_hh0, W_ih1, W_hh1,
                                       b_ih1, b_hh1, bufB);
    // head
    head_kernel<<<GRID, 128>>>(bufB, W1, b1, W2, b2, out, NROWS);
}

// round 6
// speedup vs baseline: 1.0226x; 1.0226x over previous
#include <cuda_runtime.h>

#define B_  256
#define T_  2048
#define H_  64
#define O_  2
#define NROWS (B_ * T_)
#define PF  4   // fused-scan xin prefetch depth (T_ % PF == 0)

// Scratch (device globals — no allocation allowed in kernel_launch)
__device__ float g_bufA[NROWS * H_];
__device__ float g_bufB[NROWS * H_];

// ---------- packed f32x2 helpers (sm_103a FFMA2 path) ----------
static __device__ __forceinline__ unsigned long long pack2(float lo, float hi) {
    unsigned long long r;
    asm("mov.b64 %0, {%1, %2};" : "=l"(r) : "f"(lo), "f"(hi));
    return r;
}
static __device__ __forceinline__ void unpack2(unsigned long long v, float& a, float& b) {
    asm("mov.b64 {%0, %1}, %2;" : "=f"(a), "=f"(b) : "l"(v));
}
static __device__ __forceinline__ unsigned long long fma2(unsigned long long a,
                                                          unsigned long long b,
                                                          unsigned long long c) {
    unsigned long long d;
    asm("fma.rn.f32x2 %0, %1, %2, %3;" : "=l"(d) : "l"(a), "l"(b), "l"(c));
    return d;
}
static __device__ __forceinline__ unsigned long long add2(unsigned long long a,
                                                          unsigned long long b) {
    unsigned long long d;
    asm("add.rn.f32x2 %0, %1, %2;" : "=l"(d) : "l"(a), "l"(b));
    return d;
}

// Fast tanh, rel err ~1e-7, saturates correctly.
static __device__ __forceinline__ float fast_tanh(float x) {
    float e = __expf(2.0f * x);
    return 1.0f - __fdividef(2.0f, e + 1.0f);
}

#define NAMED_BAR(id, cnt) asm volatile("bar.sync %0, %1;" :: "r"(id), "r"(cnt) : "memory")

// ============================================================================
// gemm64 (half-split): warp = (rowPair, outputHalf). Lane owns ONE output
// j = half*32 + l -> only 32 weight u64 (64 regs) => ~2x occupancy.
// 2 rows per iteration, K-paired f32x2, broadcast LDS.128 staging.
// ============================================================================
__global__ void __launch_bounds__(128) gemm64_kernel(
    const float* __restrict__ in, const float* __restrict__ W,
    const float* __restrict__ ba, const float* __restrict__ bb,
    float* __restrict__ out, int nrows)
{
    __shared__ __align__(16) unsigned long long xsm[4][2][2][32]; // [warp][buf][row01][pair]
    const int l   = threadIdx.x & 31;
    const int wrp = threadIdx.x >> 5;
    const unsigned long long* Wu = (const unsigned long long*)W;
    const unsigned long long* Iu = (const unsigned long long*)in;

    const int warpId = blockIdx.x * 4 + wrp;
    const int nw     = gridDim.x * 4;
    const int half   = warpId & 1;
    const int j      = half * 32 + l;

    unsigned long long w[32];
#pragma unroll
    for (int k = 0; k < 32; k++) w[k] = Wu[j * 32 + k];
    const float bias = ba[j] + bb[j];

    long r = (long)(warpId & ~1);    // row pair shared by warp (2p, 2p+1)
    const long stride = nw;          // 2 rows per pair, nw/2 pairs
    if (r >= nrows) return;
    unsigned long long xv0 = Iu[r * 32 + l];
    unsigned long long xv1 = (r + 1 < nrows) ? Iu[(r + 1) * 32 + l] : 0ull;
    int buf = 0;

    while (r < nrows) {
        xsm[wrp][buf][0][l] = xv0;
        xsm[wrp][buf][1][l] = xv1;
        __syncwarp();

        long rn = r + stride;
        if (rn < nrows) {
            xv0 = Iu[rn * 32 + l];
            xv1 = (rn + 1 < nrows) ? Iu[(rn + 1) * 32 + l] : 0ull;
        }

        unsigned long long a0 = pack2(bias, 0.f), a1 = 0ull;
        unsigned long long b0 = pack2(bias, 0.f), b1 = 0ull;
        const ulonglong2* xp0 = (const ulonglong2*)&xsm[wrp][buf][0][0];
        const ulonglong2* xp1 = (const ulonglong2*)&xsm[wrp][buf][1][0];
#pragma unroll
        for (int k = 0; k < 32; k += 2) {
            ulonglong2 v0 = xp0[k >> 1];   // broadcast LDS.128
            ulonglong2 v1 = xp1[k >> 1];
            a0 = fma2(w[k],     v0.x, a0);
            a1 = fma2(w[k + 1], v0.y, a1);
            b0 = fma2(w[k],     v1.x, b0);
            b1 = fma2(w[k + 1], v1.y, b1);
        }
        float s0, s1, t0, t1;
        unpack2(add2(a0, a1), s0, s1);
        unpack2(add2(b0, b1), t0, t1);
        out[r * 64 + j] = s0 + s1;
        if (r + 1 < nrows) out[(r + 1) * 64 + j] = t0 + t1;

        buf ^= 1;
        r = rn;
    }
}

// ============================================================================
// fused_scan (software-pipelined, 4 warps per batch, K-split):
// iteration i computes, CONCURRENTLY,
//   h0_i     = tanh(x_i + W_hh0 h0_{i-1})
//   h1_{i-1} = tanh(W_ih1 h0_{i-1} + b1 + W_hh1 h1_{i-2})
// Block = 256 threads = 2 batches x 4 warps (each SMSP hosts 2 warps from
// DIFFERENT batches -> latency overlap). Within a batch, lane owns output
// j = wq*16 + (l&15) and K-half (l>>4): 16 k-pairs x 3 matvecs = 48 fma2.
// Halves combined via shfl_xor(16). ONE named barrier (128 thr) per step.
// ============================================================================
__global__ void __launch_bounds__(256) fused_scan_kernel(
    const float* __restrict__ xin0,
    const float* __restrict__ Whh0, const float* __restrict__ Wih1,
    const float* __restrict__ Whh1,
    const float* __restrict__ b_ih1, const float* __restrict__ b_hh1,
    float* __restrict__ h1out)
{
    __shared__ __align__(16) float h0sm[2][2][64];
    __shared__ __align__(16) float h1sm[2][2][64];
    const int l     = threadIdx.x & 31;
    const int wid   = threadIdx.x >> 5;
    const int bl    = wid >> 2;            // batch slot (0..1)
    const int wq    = wid & 3;             // warp-in-batch (0..3)
    const int j     = wq * 16 + (l & 15);  // owned output
    const int kh    = l >> 4;              // K-half (0: pairs 0-15, 1: 16-31)
    const bool lead = (l < 16);            // lane that stores results
    const int b     = blockIdx.x * 2 + bl;
    const int barid = bl + 1;

    const unsigned long long* W0u = (const unsigned long long*)Whh0;
    const unsigned long long* Wxu = (const unsigned long long*)Wih1;
    const unsigned long long* W1u = (const unsigned long long*)Whh1;
    unsigned long long w0[16], wx[16], w1[16];
#pragma unroll
    for (int m = 0; m < 16; m++) {
        const int k = kh * 16 + m;
        w0[m] = W0u[j * 32 + k];
        wx[m] = Wxu[j * 32 + k];
        w1[m] = W1u[j * 32 + k];
    }
    const float bias1g = lead ? (b_ih1[j] + b_hh1[j]) : 0.f;

    if (lead) {
        h0sm[bl][0][j] = 0.f;   // h0_{-1}
        h1sm[bl][0][j] = 0.f;   // h1_{-2} (placeholder)
    }

    const float* xb = xin0  + (long)b * T_ * 64;
    float*       hb = h1out + (long)b * T_ * 64;

    float xs[PF];
#pragma unroll
    for (int s = 0; s < PF; s++) xs[s] = xb[s * 64 + j];

    NAMED_BAR(barid, 128);

    int p = 0;
    for (int tb = 0; tb < T_; tb += PF) {
#pragma unroll
        for (int u = 0; u < PF; u++) {
            const int i = tb + u;
            const float xv = lead ? xs[u] : 0.f;
            if (i + PF < T_) xs[u] = xb[(i + PF) * 64 + j];

            // h0sm[bl][p] = h0_{i-1}, h1sm[bl][p] = h1_{i-2}
            unsigned long long a0 = pack2(xv, 0.f), a1 = 0ull;       // Whh0.h0
            unsigned long long c0 = pack2(bias1g, 0.f), c1 = 0ull;   // Wih1.h0
            unsigned long long d0 = 0ull, d1 = 0ull;                 // Whh1.h1
            const ulonglong2* hp0 = (const ulonglong2*)&h0sm[bl][p][kh * 32];
            const ulonglong2* hp1 = (const ulonglong2*)&h1sm[bl][p][kh * 32];
#pragma unroll
            for (int m = 0; m < 16; m += 2) {
                ulonglong2 v = hp0[m >> 1];   // h0_{i-1}: one load, two uses
                ulonglong2 g = hp1[m >> 1];   // h1_{i-2}
                a0 = fma2(w0[m],     v.x, a0);
                a1 = fma2(w0[m + 1], v.y, a1);
                c0 = fma2(wx[m],     v.x, c0);
                c1 = fma2(wx[m + 1], v.y, c1);
                d0 = fma2(w1[m],     g.x, d0);
                d1 = fma2(w1[m + 1], g.y, d1);
            }
            float s0, s1, e0, e1;
            unpack2(add2(a0, a1), s0, s1);
            unpack2(add2(add2(c0, c1), add2(d0, d1)), e0, e1);
            float sh = s0 + s1;
            float eh = e0 + e1;
            sh += __shfl_xor_sync(0xffffffffu, sh, 16);   // combine K-halves
            eh += __shfl_xor_sync(0xffffffffu, eh, 16);

            const float h0v = fast_tanh(sh);
            float h1v = fast_tanh(eh);          // = h1_{i-1}
            if (i == 0) h1v = 0.f;              // h1_{-1} := 0

            if (lead) {
                if (i) hb[(i - 1) * 64 + j] = h1v;
                h0sm[bl][p ^ 1][j] = h0v;
                h1sm[bl][p ^ 1][j] = h1v;
            }
            NAMED_BAR(barid, 128);
            p ^= 1;
        }
    }

    // Epilogue: h1_{T-1} = tanh(Wih1 h0_{T-1} + b1 + Whh1 h1_{T-2})
    {
        unsigned long long c0 = pack2(bias1g, 0.f), c1 = 0ull;
        unsigned long long d0 = 0ull, d1 = 0ull;
        const ulonglong2* hp0 = (const ulonglong2*)&h0sm[bl][p][kh * 32];
        const ulonglong2* hp1 = (const ulonglong2*)&h1sm[bl][p][kh * 32];
#pragma unroll
        for (int m = 0; m < 16; m += 2) {
            ulonglong2 v = hp0[m >> 1];
            ulonglong2 g = hp1[m >> 1];
            c0 = fma2(wx[m],     v.x, c0);
            c1 = fma2(wx[m + 1], v.y, c1);
            d0 = fma2(w1[m],     g.x, d0);
            d1 = fma2(w1[m + 1], g.y, d1);
        }
        float e0, e1;
        unpack2(add2(add2(c0, c1), add2(d0, d1)), e0, e1);
        float eh = e0 + e1;
        eh += __shfl_xor_sync(0xffffffffu, eh, 16);
        if (lead) hb[(T_ - 1) * 64 + j] = fast_tanh(eh);
    }
}

// ============================================================================
// head: z = relu(h W1^T + b1); out = z W2^T + b2  (O=2). 2 rows/iter.
// ============================================================================
__global__ void __launch_bounds__(128) head_kernel(
    const float* __restrict__ hin, const float* __restrict__ W1,
    const float* __restrict__ b1, const float* __restrict__ W2,
    const float* __restrict__ b2, float* __restrict__ out, int nrows)
{
    __shared__ __align__(16) unsigned long long xsm[4][2][2][32];
    const int l   = threadIdx.x & 31;
    const int wrp = threadIdx.x >> 5;
    const unsigned long long* Wu = (const unsigned long long*)W1;
    const unsigned long long* Iu = (const unsigned long long*)hin;

    unsigned long long wl[32], wh[32];
#pragma unroll
    for (int k = 0; k < 32; k++) {
        wl[k] = Wu[l * 32 + k];
        wh[k] = Wu[(l + 32) * 32 + k];
    }
    const float biasl = b1[l], biash = b1[l + 32];
    const float w20l = W2[l],      w20h = W2[32 + l];
    const float w21l = W2[64 + l], w21h = W2[96 + l];
    const float b20 = b2[0], b21 = b2[1];

    const int warpId = blockIdx.x * 4 + wrp;
    const int nw     = gridDim.x * 4;
    const long stride = 2L * nw;

    long r = 2L * warpId;
    if (r >= nrows) return;
    unsigned long long xv0 = Iu[r * 32 + l];
    unsigned long long xv1 = (r + 1 < nrows) ? Iu[(r + 1) * 32 + l] : 0ull;
    int buf = 0;

    while (r < nrows) {
        xsm[wrp][buf][0][l] = xv0;
        xsm[wrp][buf][1][l] = xv1;
        __syncwarp();

        long rn = r + stride;
        if (rn < nrows) {
            xv0 = Iu[rn * 32 + l];
            xv1 = (rn + 1 < nrows) ? Iu[(rn + 1) * 32 + l] : 0ull;
        }

        unsigned long long a0 = pack2(biasl, 0.f), a1 = 0ull;
        unsigned long long c0 = pack2(biash, 0.f), c1 = 0ull;
        unsigned long long d0 = pack2(biasl, 0.f), d1 = 0ull;
        unsigned long long e0 = pack2(biash, 0.f), e1 = 0ull;
        const ulonglong2* xp0 = (const ulonglong2*)&xsm[wrp][buf][0][0];
        const ulonglong2* xp1 = (const ulonglong2*)&xsm[wrp][buf][1][0];
#pragma unroll
        for (int k = 0; k < 32; k += 2) {
            ulonglong2 v0 = xp0[k >> 1];
            ulonglong2 v1 = xp1[k >> 1];
            a0 = fma2(wl[k],     v0.x, a0);
            a1 = fma2(wl[k + 1], v0.y, a1);
            c0 = fma2(wh[k],     v0.x, c0);
            c1 = fma2(wh[k + 1], v0.y, c1);
            d0 = fma2(wl[k],     v1.x, d0);
            d1 = fma2(wl[k + 1], v1.y, d1);
            e0 = fma2(wh[k],     v1.x, e0);
            e1 = fma2(wh[k + 1], v1.y, e1);
        }
        float s0, s1, t0, t1, u0, u1, q0, q1;
        unpack2(add2(a0, a1), s0, s1);
        unpack2(add2(c0, c1), t0, t1);
        unpack2(add2(d0, d1), u0, u1);
        unpack2(add2(e0, e1), q0, q1);

        float z0 = fmaxf(s0 + s1, 0.f);
        float z1 = fmaxf(t0 + t1, 0.f);
        float y0 = fmaxf(u0 + u1, 0.f);
        float y1 = fmaxf(q0 + q1, 0.f);

        float p0 = z0 * w20l + z1 * w20h;
        float p1 = z0 * w21l + z1 * w21h;
        float p2 = y0 * w20l + y1 * w20h;
        float p3 = y0 * w21l + y1 * w21h;
#pragma unroll
        for (int off = 16; off; off >>= 1) {
            p0 += __shfl_xor_sync(0xffffffffu, p0, off);
            p1 += __shfl_xor_sync(0xffffffffu, p1, off);
            p2 += __shfl_xor_sync(0xffffffffu, p2, off);
            p3 += __shfl_xor_sync(0xffffffffu, p3, off);
        }
        if (l == 0) {
            *reinterpret_cast<float2*>(&out[r * 2]) = make_float2(p0 + b20, p1 + b21);
            if (r + 1 < nrows)
                *reinterpret_cast<float2*>(&out[(r + 1) * 2]) = make_float2(p2 + b20, p3 + b21);
        }

        buf ^= 1;
        r = rn;
    }
}

// ============================================================================
extern "C" void kernel_launch(void* const* d_in, const int* in_sizes, int n_in,
                              void* d_out, int out_size)
{
    const float* x     = (const float*)d_in[0];
    const float* W_ih0 = (const float*)d_in[1];
    const float* W_hh0 = (const float*)d_in[2];
    const float* b_ih0 = (const float*)d_in[3];
    const float* b_hh0 = (const float*)d_in[4];
    const float* W_ih1 = (const float*)d_in[5];
    const float* W_hh1 = (const float*)d_in[6];
    const float* b_ih1 = (const float*)d_in[7];
    const float* b_hh1 = (const float*)d_in[8];
    const float* W1    = (const float*)d_in[9];
    const float* b1    = (const float*)d_in[10];
    const float* W2    = (const float*)d_in[11];
    const float* b2    = (const float*)d_in[12];
    float* out = (float*)d_out;

    static float* bufA = nullptr;
    static float* bufB = nullptr;
    if (!bufA) {
        cudaGetSymbolAddress((void**)&bufA, g_bufA);
        cudaGetSymbolAddress((void**)&bufB, g_bufB);
    }

    const int GRID = 1184;

    // xin0 = x W_ih0^T + b_ih0 + b_hh0
    gemm64_kernel<<<GRID, 128>>>(x, W_ih0, b_ih0, b_hh0, bufA, NROWS);
    // both RNN layers, software-pipelined, 4 warps/batch -> h1
    fused_scan_kernel<<<B_ / 2, 256>>>(bufA, W_hh0, W_ih1, W_hh1,
                                       b_ih1, b_hh1, bufB);
    // head
    head_kernel<<<GRID, 128>>>(bufB, W1, b1, W2, b2, out, NROWS);
}